// round 11
// baseline (speedup 1.0000x reference)
#include <cuda_runtime.h>
#include <cuda_fp16.h>
#include <cstdint>

// Problem constants (fixed by the dataset)
#define BATCH 2
#define SEQ   512
#define BS    (BATCH * SEQ)      // 1024 tokens
#define FDIM  16384              // n_features
#define DDIM  768                // d_model
#define MCON  262144             // n_connections

// SpMM tile
#define TI 32    // i rows per block
#define TT 256   // tokens per block (lane owns 8 via one uint4 of halves)

// Prep grids (transpose tiles are 64 src rows x 32 src cols)
#define T1_BLOCKS ((FDIM / 32) * (DDIM / 64))   // 6144 up_decoder tiles
#define T2_BLOCKS ((FDIM / 32) * (BS / 64))     // 8192 up_facts tiles
#define RP_BLOCKS (((FDIM + 1) + 255) / 256)    // 65 rowptr blocks

// Static device scratch (no allocations allowed in kernel_launch)
__device__ __half g_udT[(size_t)FDIM * DDIM];    // up_decoder transposed: [F, D], fp16
__device__ __half g_ufT[(size_t)FDIM * BS];      // up_facts transposed:   [F, BS], fp16
__device__ float  g_values[MCON];                // per-connection value (fp32)
__device__ int    g_rowptr[FDIM + 1];            // CSR row pointers over sorted i

// ---------------------------------------------------------------------------
// Transpose tile helper (R7-tuned): 64 src rows x 32 src cols, fp32 -> fp16,
// half2-vectorized gmem stores (full 128B transactions).
// ---------------------------------------------------------------------------
__device__ __forceinline__ void transpose_tile_f2h(const float* __restrict__ src,
                                                   __half* __restrict__ dst,
                                                   int R, int C, int bx, int by,
                                                   int x, int y) {
    __shared__ float tile[64][33];
    const int c0 = bx * 32;
    const int r0 = by * 64;

#pragma unroll
    for (int k = 0; k < 64; k += 8) {
        tile[y + k][x] = src[(size_t)(r0 + y + k) * C + c0 + x];
    }
    __syncthreads();

    __half2* dst2 = reinterpret_cast<__half2*>(dst);
    const int rhalf = R >> 1;
#pragma unroll
    for (int dr = 0; dr < 32; dr += 8) {
        int row = dr + y;             // src col / dst row within tile
        __half2 v = __floats2half2_rn(tile[2 * x][row], tile[2 * x + 1][row]);
        dst2[(size_t)(c0 + row) * rhalf + (r0 >> 1) + x] = v;
    }
}

// ---------------------------------------------------------------------------
// Kernel A: up_decoder transpose + rowptr (everything values_kernel needs).
// ---------------------------------------------------------------------------
__global__ void prep_ud_kernel(const float* __restrict__ up_decoder,
                               const int* __restrict__ i_indices,
                               __half* __restrict__ udT) {
    cudaTriggerProgrammaticLaunchCompletion();
    const int b = blockIdx.x;
    const int x = threadIdx.x & 31;
    const int y = threadIdx.x >> 5;

    if (b < T1_BLOCKS) {
        int bx = b % (FDIM / 32);
        int by = b / (FDIM / 32);
        transpose_tile_f2h(up_decoder, udT, DDIM, FDIM, bx, by, x, y);
    } else {
        // rowptr: g_rowptr[f] = lower_bound(i_indices, f)
        int f = (b - T1_BLOCKS) * 256 + threadIdx.x;
        if (f > FDIM) return;
        int lo = 0, hi = MCON;
        while (lo < hi) {
            int mid = (lo + hi) >> 1;
            if (i_indices[mid] < f) lo = mid + 1;
            else hi = mid;
        }
        g_rowptr[f] = lo;
    }
}

// ---------------------------------------------------------------------------
// Kernel C (side stream): up_facts transpose — DRAM-bound, overlaps the
// L2-bound values_kernel.
// ---------------------------------------------------------------------------
__global__ void prep_uf_kernel(const float* __restrict__ up_facts,
                               __half* __restrict__ ufT) {
    const int b = blockIdx.x;
    const int x = threadIdx.x & 31;
    const int y = threadIdx.x >> 5;
    int bx = b % (FDIM / 32);
    int by = b / (FDIM / 32);
    transpose_tile_f2h(up_facts, ufT, BS, FDIM, bx, by, x, y);
}

// ---------------------------------------------------------------------------
// Kernel B: SDDMM values. TWO warps per i-row (even/odd m split).
// E[i] held fp32 in registers, layout-matched to the fp16 U row loads.
// PDL: E loads (independent of prep) run before the grid sync.
// ---------------------------------------------------------------------------
__global__ void values_kernel(const float* __restrict__ down_encoder,
                              const int* __restrict__ j_indices) {
    cudaTriggerProgrammaticLaunchCompletion();
    int gwarp = (blockIdx.x * blockDim.x + threadIdx.x) >> 5;
    int lane = threadIdx.x & 31;
    if (gwarp >= FDIM * 2) {
        cudaGridDependencySynchronize();
        return;
    }
    const int i      = gwarp >> 1;
    const int parity = gwarp & 1;

    // Prologue independent of prep: load E[i].
    const float4* E4 = reinterpret_cast<const float4*>(down_encoder + (size_t)i * DDIM);
    float4 ea[3], eb[3];
#pragma unroll
    for (int k = 0; k < 3; k++) {
        int base = 2 * (k * 32 + lane);
        ea[k] = E4[base];
        eb[k] = E4[base + 1];
    }

    // Wait for prep_ud (udT + rowptr) to be complete and visible.
    cudaGridDependencySynchronize();

    int m1 = g_rowptr[i + 1];
    for (int m = g_rowptr[i] + parity; m < m1; m += 2) {
        int j = __ldg(&j_indices[m]);
        const uint4* U = reinterpret_cast<const uint4*>(g_udT + (size_t)j * DDIM);
        float s = 0.0f;
#pragma unroll
        for (int k = 0; k < 3; k++) {
            uint4 u = U[k * 32 + lane];
            float2 f0 = __half22float2(*reinterpret_cast<__half2*>(&u.x));
            float2 f1 = __half22float2(*reinterpret_cast<__half2*>(&u.y));
            float2 f2 = __half22float2(*reinterpret_cast<__half2*>(&u.z));
            float2 f3 = __half22float2(*reinterpret_cast<__half2*>(&u.w));
            s += ea[k].x * f0.x + ea[k].y * f0.y + ea[k].z * f1.x + ea[k].w * f1.y;
            s += eb[k].x * f2.x + eb[k].y * f2.y + eb[k].z * f3.x + eb[k].w * f3.y;
        }
#pragma unroll
        for (int off = 16; off; off >>= 1)
            s += __shfl_xor_sync(0xffffffffu, s, off);
        if (lane == 0) g_values[m] = s;
    }
}

// ---------------------------------------------------------------------------
// Kernel D: fused SpMM + output transpose, fp16 activations, fp32 accumulate.
// Block computes [TI=32 i-rows] x [TT=256 tokens]. Warp handles 4 i-rows;
// lane owns 8 consecutive tokens. Staged in smem, coalesced 128B out rows.
// ---------------------------------------------------------------------------
__global__ void spmm_fused_kernel(const int* __restrict__ j_indices,
                                  float* __restrict__ out) {
    __shared__ float tile[TI][TT + 1];   // pad 1: conflict-free column reads

    const int i_base = blockIdx.x * TI;
    const int tok0   = blockIdx.y * TT;
    const int warp   = threadIdx.x >> 5;
    const int lane   = threadIdx.x & 31;

    const uint4* uf = reinterpret_cast<const uint4*>(g_ufT);
    const int tcol = (tok0 >> 3) + lane;   // uint4 index into a ufT row (BS/8 per row)

    for (int ii = warp; ii < TI; ii += 8) {
        const int i = i_base + ii;
        int m0 = g_rowptr[i];
        int m1 = g_rowptr[i + 1];

        float acc[8];
#pragma unroll
        for (int t = 0; t < 8; t++) acc[t] = 0.0f;

        int m = m0;
        for (; m + 1 < m1; m += 2) {
            float v0 = g_values[m];
            float v1 = g_values[m + 1];
            int j0 = __ldg(&j_indices[m]);
            int j1 = __ldg(&j_indices[m + 1]);
            uint4 u0 = uf[(size_t)j0 * (BS / 8) + tcol];
            uint4 u1 = uf[(size_t)j1 * (BS / 8) + tcol];
            {
                float2 f0 = __half22float2(*reinterpret_cast<__half2*>(&u0.x));
                float2 f1 = __half22float2(*reinterpret_cast<__half2*>(&u0.y));
                float2 f2 = __half22float2(*reinterpret_cast<__half2*>(&u0.z));
                float2 f3 = __half22float2(*reinterpret_cast<__half2*>(&u0.w));
                acc[0] += v0 * f0.x; acc[1] += v0 * f0.y;
                acc[2] += v0 * f1.x; acc[3] += v0 * f1.y;
                acc[4] += v0 * f2.x; acc[5] += v0 * f2.y;
                acc[6] += v0 * f3.x; acc[7] += v0 * f3.y;
            }
            {
                float2 f0 = __half22float2(*reinterpret_cast<__half2*>(&u1.x));
                float2 f1 = __half22float2(*reinterpret_cast<__half2*>(&u1.y));
                float2 f2 = __half22float2(*reinterpret_cast<__half2*>(&u1.z));
                float2 f3 = __half22float2(*reinterpret_cast<__half2*>(&u1.w));
                acc[0] += v1 * f0.x; acc[1] += v1 * f0.y;
                acc[2] += v1 * f1.x; acc[3] += v1 * f1.y;
                acc[4] += v1 * f2.x; acc[5] += v1 * f2.y;
                acc[6] += v1 * f3.x; acc[7] += v1 * f3.y;
            }
        }
        for (; m < m1; m++) {
            float v = g_values[m];
            int j = __ldg(&j_indices[m]);
            uint4 u = uf[(size_t)j * (BS / 8) + tcol];
            float2 f0 = __half22float2(*reinterpret_cast<__half2*>(&u.x));
            float2 f1 = __half22float2(*reinterpret_cast<__half2*>(&u.y));
            float2 f2 = __half22float2(*reinterpret_cast<__half2*>(&u.z));
            float2 f3 = __half22float2(*reinterpret_cast<__half2*>(&u.w));
            acc[0] += v * f0.x; acc[1] += v * f0.y;
            acc[2] += v * f1.x; acc[3] += v * f1.y;
            acc[4] += v * f2.x; acc[5] += v * f2.y;
            acc[6] += v * f3.x; acc[7] += v * f3.y;
        }

#pragma unroll
        for (int t = 0; t < 8; t++)
            tile[ii][lane * 8 + t] = acc[t];
    }
    __syncthreads();

    // Write out: warp writes one token row per iter (32 consecutive i's = 128B)
    for (int t = warp; t < TT; t += 8) {
        out[(size_t)(tok0 + t) * FDIM + i_base + lane] = tile[lane][t];
    }
}

// ---------------------------------------------------------------------------
// Launch DAG:
//   s0: A(ud transpose + rowptr) -> B(values, PDL) -> [wait C] -> D(spmm)
//   s1: C(uf transpose)   (forked from s0, joined before D)
// ---------------------------------------------------------------------------
extern "C" void kernel_launch(void* const* d_in, const int* in_sizes, int n_in,
                              void* d_out, int out_size) {
    const float* up_facts     = (const float*)d_in[0];   // [B, S, F]
    const float* down_encoder = (const float*)d_in[1];   // [F, D]
    const float* up_decoder   = (const float*)d_in[2];   // [D, F]
    const int*   i_indices    = (const int*)d_in[3];     // [M], sorted, int32
    const int*   j_indices    = (const int*)d_in[4];     // [M], int32
    float*       out          = (float*)d_out;           // [B, S, F]

    __half* udT; cudaGetSymbolAddress((void**)&udT, g_udT);
    __half* ufT; cudaGetSymbolAddress((void**)&ufT, g_ufT);

    // Host-side handles: created per call, intentionally NOT destroyed.
    // kernel_launch only executes for correctness + graph capture (replays
    // use the captured graph), so this leaks a handful of host objects, and
    // avoids destroying a stream/event that the active capture references.
    cudaStream_t s1;
    cudaStreamCreateWithFlags(&s1, cudaStreamNonBlocking);
    cudaEvent_t eFork, eC;
    cudaEventCreateWithFlags(&eFork, cudaEventDisableTiming);
    cudaEventCreateWithFlags(&eC, cudaEventDisableTiming);

    // Fork side stream from the (captured) default stream.
    cudaEventRecord(eFork, 0);
    cudaStreamWaitEvent(s1, eFork, 0);

    // C: up_facts transpose on s1 (independent; joined before spmm).
    prep_uf_kernel<<<T2_BLOCKS, 256, 0, s1>>>(up_facts, ufT);
    cudaEventRecord(eC, s1);

    // A: up_decoder transpose + rowptr on s0.
    prep_ud_kernel<<<T1_BLOCKS + RP_BLOCKS, 256>>>(up_decoder, i_indices, udT);

    // B: values on s0, PDL-overlapped with A's tail.
    {
        int threads = 256;
        long long total_threads = (long long)FDIM * 2 * 32;
        int blocks = (int)((total_threads + threads - 1) / threads);

        cudaLaunchConfig_t cfg = {};
        cfg.gridDim  = dim3((unsigned)blocks);
        cfg.blockDim = dim3((unsigned)threads);
        cfg.dynamicSmemBytes = 0;
        cfg.stream = 0;
        cudaLaunchAttribute attr[1];
        attr[0].id = cudaLaunchAttributeProgrammaticStreamSerialization;
        attr[0].val.programmaticStreamSerializationAllowed = 1;
        cfg.attrs = attr;
        cfg.numAttrs = 1;
        cudaLaunchKernelEx(&cfg, values_kernel, down_encoder, j_indices);
    }

    // Join: spmm needs ufT from s1.
    cudaStreamWaitEvent(0, eC, 0);

    // D: fused SpMM + output transpose.
    {
        dim3 grid(FDIM / TI, BS / TT);
        spmm_fused_kernel<<<grid, 256>>>(j_indices, out);
    }
}

// round 12
// speedup vs baseline: 1.0906x; 1.0906x over previous
#include <cuda_runtime.h>
#include <cuda_fp16.h>
#include <cstdint>

// Problem constants (fixed by the dataset)
#define BATCH 2
#define SEQ   512
#define BS    (BATCH * SEQ)      // 1024 tokens
#define FDIM  16384              // n_features
#define DDIM  768                // d_model
#define MCON  262144             // n_connections

// SpMM tile
#define TI 16    // i rows per block (16.5KB smem -> occupancy no longer smem-bound)
#define TT 256   // tokens per block (lane owns 8 via one uint4 of halves)

// Prep grids (transpose tiles are 64 src rows x 32 src cols)
#define T1_BLOCKS ((FDIM / 32) * (DDIM / 64))   // 6144 up_decoder tiles
#define T2_BLOCKS ((FDIM / 32) * (BS / 64))     // 8192 up_facts tiles
#define RP_BLOCKS (((FDIM + 1) + 255) / 256)    // 65 rowptr blocks

// Static device scratch (no allocations allowed in kernel_launch)
__device__ __half g_udT[(size_t)FDIM * DDIM];    // up_decoder transposed: [F, D], fp16
__device__ __half g_ufT[(size_t)FDIM * BS];      // up_facts transposed:   [F, BS], fp16
__device__ float  g_values[MCON];                // per-connection value (fp32)
__device__ int    g_rowptr[FDIM + 1];            // CSR row pointers over sorted i

// ---------------------------------------------------------------------------
// Transpose tile helper (R7-tuned): 64 src rows x 32 src cols, fp32 -> fp16,
// half2-vectorized gmem stores (full 128B transactions).
// ---------------------------------------------------------------------------
__device__ __forceinline__ void transpose_tile_f2h(const float* __restrict__ src,
                                                   __half* __restrict__ dst,
                                                   int R, int C, int bx, int by,
                                                   int x, int y) {
    __shared__ float tile[64][33];
    const int c0 = bx * 32;
    const int r0 = by * 64;

#pragma unroll
    for (int k = 0; k < 64; k += 8) {
        tile[y + k][x] = src[(size_t)(r0 + y + k) * C + c0 + x];
    }
    __syncthreads();

    __half2* dst2 = reinterpret_cast<__half2*>(dst);
    const int rhalf = R >> 1;
#pragma unroll
    for (int dr = 0; dr < 32; dr += 8) {
        int row = dr + y;             // src col / dst row within tile
        __half2 v = __floats2half2_rn(tile[2 * x][row], tile[2 * x + 1][row]);
        dst2[(size_t)(c0 + row) * rhalf + (r0 >> 1) + x] = v;
    }
}

// ---------------------------------------------------------------------------
// Kernel A: up_decoder transpose + rowptr (everything values_kernel needs).
// ---------------------------------------------------------------------------
__global__ void prep_ud_kernel(const float* __restrict__ up_decoder,
                               const int* __restrict__ i_indices,
                               __half* __restrict__ udT) {
    cudaTriggerProgrammaticLaunchCompletion();
    const int b = blockIdx.x;
    const int x = threadIdx.x & 31;
    const int y = threadIdx.x >> 5;

    if (b < T1_BLOCKS) {
        int bx = b % (FDIM / 32);
        int by = b / (FDIM / 32);
        transpose_tile_f2h(up_decoder, udT, DDIM, FDIM, bx, by, x, y);
    } else {
        // rowptr: g_rowptr[f] = lower_bound(i_indices, f)
        int f = (b - T1_BLOCKS) * 256 + threadIdx.x;
        if (f > FDIM) return;
        int lo = 0, hi = MCON;
        while (lo < hi) {
            int mid = (lo + hi) >> 1;
            if (i_indices[mid] < f) lo = mid + 1;
            else hi = mid;
        }
        g_rowptr[f] = lo;
    }
}

// ---------------------------------------------------------------------------
// Kernel C (side stream): up_facts transpose — DRAM-bound, overlaps the
// L2-bound values_kernel.
// ---------------------------------------------------------------------------
__global__ void prep_uf_kernel(const float* __restrict__ up_facts,
                               __half* __restrict__ ufT) {
    const int b = blockIdx.x;
    const int x = threadIdx.x & 31;
    const int y = threadIdx.x >> 5;
    int bx = b % (FDIM / 32);
    int by = b / (FDIM / 32);
    transpose_tile_f2h(up_facts, ufT, BS, FDIM, bx, by, x, y);
}

// ---------------------------------------------------------------------------
// Kernel B: SDDMM values. TWO warps per i-row (even/odd m split).
// E[i] held fp32 in registers, layout-matched to the fp16 U row loads.
// PDL: E loads (independent of prep) run before the grid sync.
// ---------------------------------------------------------------------------
__global__ void values_kernel(const float* __restrict__ down_encoder,
                              const int* __restrict__ j_indices) {
    cudaTriggerProgrammaticLaunchCompletion();
    int gwarp = (blockIdx.x * blockDim.x + threadIdx.x) >> 5;
    int lane = threadIdx.x & 31;
    if (gwarp >= FDIM * 2) {
        cudaGridDependencySynchronize();
        return;
    }
    const int i      = gwarp >> 1;
    const int parity = gwarp & 1;

    // Prologue independent of prep: load E[i].
    const float4* E4 = reinterpret_cast<const float4*>(down_encoder + (size_t)i * DDIM);
    float4 ea[3], eb[3];
#pragma unroll
    for (int k = 0; k < 3; k++) {
        int base = 2 * (k * 32 + lane);
        ea[k] = E4[base];
        eb[k] = E4[base + 1];
    }

    // Wait for prep_ud (udT + rowptr) to be complete and visible.
    cudaGridDependencySynchronize();

    int m1 = g_rowptr[i + 1];
    for (int m = g_rowptr[i] + parity; m < m1; m += 2) {
        int j = __ldg(&j_indices[m]);
        const uint4* U = reinterpret_cast<const uint4*>(g_udT + (size_t)j * DDIM);
        float s = 0.0f;
#pragma unroll
        for (int k = 0; k < 3; k++) {
            uint4 u = U[k * 32 + lane];
            float2 f0 = __half22float2(*reinterpret_cast<__half2*>(&u.x));
            float2 f1 = __half22float2(*reinterpret_cast<__half2*>(&u.y));
            float2 f2 = __half22float2(*reinterpret_cast<__half2*>(&u.z));
            float2 f3 = __half22float2(*reinterpret_cast<__half2*>(&u.w));
            s += ea[k].x * f0.x + ea[k].y * f0.y + ea[k].z * f1.x + ea[k].w * f1.y;
            s += eb[k].x * f2.x + eb[k].y * f2.y + eb[k].z * f3.x + eb[k].w * f3.y;
        }
#pragma unroll
        for (int off = 16; off; off >>= 1)
            s += __shfl_xor_sync(0xffffffffu, s, off);
        if (lane == 0) g_values[m] = s;
    }
}

// ---------------------------------------------------------------------------
// FMA helper: acc[0..7] += v * (8 halves in u)
// ---------------------------------------------------------------------------
__device__ __forceinline__ void fma8(float* acc, float v, const uint4& u) {
    float2 f0 = __half22float2(*reinterpret_cast<const __half2*>(&u.x));
    float2 f1 = __half22float2(*reinterpret_cast<const __half2*>(&u.y));
    float2 f2 = __half22float2(*reinterpret_cast<const __half2*>(&u.z));
    float2 f3 = __half22float2(*reinterpret_cast<const __half2*>(&u.w));
    acc[0] += v * f0.x; acc[1] += v * f0.y;
    acc[2] += v * f1.x; acc[3] += v * f1.y;
    acc[4] += v * f2.x; acc[5] += v * f2.y;
    acc[6] += v * f3.x; acc[7] += v * f3.y;
}

// ---------------------------------------------------------------------------
// Kernel D: fused SpMM + output transpose, fp16 activations, fp32 accumulate.
// Block computes [TI=16 i-rows] x [TT=256 tokens]. Warp handles 2 i-rows;
// lane owns 8 consecutive tokens. 4-way m-unroll for 4 independent
// j->u gather chains per warp. smem 16.5KB; regs capped for >=5 blocks/SM.
// ---------------------------------------------------------------------------
__global__ void __launch_bounds__(256, 5)
spmm_fused_kernel(const int* __restrict__ j_indices,
                  float* __restrict__ out) {
    cudaGridDependencySynchronize();

    __shared__ float tile[TI][TT + 1];   // pad 1: conflict-free column reads

    const int i_base = blockIdx.x * TI;
    const int tok0   = blockIdx.y * TT;
    const int warp   = threadIdx.x >> 5;
    const int lane   = threadIdx.x & 31;

    const uint4* uf = reinterpret_cast<const uint4*>(g_ufT);
    const int tcol = (tok0 >> 3) + lane;   // uint4 index into a ufT row (BS/8 per row)

    for (int ii = warp; ii < TI; ii += 8) {
        const int i = i_base + ii;
        int m0 = g_rowptr[i];
        int m1 = g_rowptr[i + 1];

        float acc[8];
#pragma unroll
        for (int t = 0; t < 8; t++) acc[t] = 0.0f;

        int m = m0;
        // 4-way unroll: 4 independent j->u chains in flight.
        for (; m + 3 < m1; m += 4) {
            int j0 = __ldg(&j_indices[m]);
            int j1 = __ldg(&j_indices[m + 1]);
            int j2 = __ldg(&j_indices[m + 2]);
            int j3 = __ldg(&j_indices[m + 3]);
            float v0 = g_values[m];
            float v1 = g_values[m + 1];
            float v2 = g_values[m + 2];
            float v3 = g_values[m + 3];
            uint4 u0 = uf[(size_t)j0 * (BS / 8) + tcol];
            uint4 u1 = uf[(size_t)j1 * (BS / 8) + tcol];
            uint4 u2 = uf[(size_t)j2 * (BS / 8) + tcol];
            uint4 u3 = uf[(size_t)j3 * (BS / 8) + tcol];
            fma8(acc, v0, u0);
            fma8(acc, v1, u1);
            fma8(acc, v2, u2);
            fma8(acc, v3, u3);
        }
        for (; m < m1; m++) {
            int j = __ldg(&j_indices[m]);
            float v = g_values[m];
            uint4 u = uf[(size_t)j * (BS / 8) + tcol];
            fma8(acc, v, u);
        }

#pragma unroll
        for (int t = 0; t < 8; t++)
            tile[ii][lane * 8 + t] = acc[t];
    }
    __syncthreads();

    // Write out: each half-warp writes one token row of 16 consecutive i's
    // (64B), two rows per warp per iteration. smem column reads conflict-free
    // (row stride 257 floats).
    {
        const int il = lane & 15;
        for (int t = warp * 2 + (lane >> 4); t < TT; t += 16) {
            out[(size_t)(tok0 + t) * FDIM + i_base + il] = tile[il][t];
        }
    }
}

// ---------------------------------------------------------------------------
// Launch DAG:
//   s0: A(ud transpose + rowptr) -> B(values, PDL) -> [wait C] -> D(spmm)
//   s1: C(uf transpose)   (forked from s0, joined before D)
// ---------------------------------------------------------------------------
extern "C" void kernel_launch(void* const* d_in, const int* in_sizes, int n_in,
                              void* d_out, int out_size) {
    const float* up_facts     = (const float*)d_in[0];   // [B, S, F]
    const float* down_encoder = (const float*)d_in[1];   // [F, D]
    const float* up_decoder   = (const float*)d_in[2];   // [D, F]
    const int*   i_indices    = (const int*)d_in[3];     // [M], sorted, int32
    const int*   j_indices    = (const int*)d_in[4];     // [M], int32
    float*       out          = (float*)d_out;           // [B, S, F]

    __half* udT; cudaGetSymbolAddress((void**)&udT, g_udT);
    __half* ufT; cudaGetSymbolAddress((void**)&ufT, g_ufT);

    // Host-side handles: created per call, intentionally NOT destroyed.
    // kernel_launch only executes for correctness + graph capture (replays
    // use the captured graph), so this leaks a handful of host objects, and
    // avoids destroying a stream/event that the active capture references.
    cudaStream_t s1;
    cudaStreamCreateWithFlags(&s1, cudaStreamNonBlocking);
    cudaEvent_t eFork, eC;
    cudaEventCreateWithFlags(&eFork, cudaEventDisableTiming);
    cudaEventCreateWithFlags(&eC, cudaEventDisableTiming);

    // Fork side stream from the (captured) default stream.
    cudaEventRecord(eFork, 0);
    cudaStreamWaitEvent(s1, eFork, 0);

    // C: up_facts transpose on s1 (independent; joined before spmm).
    prep_uf_kernel<<<T2_BLOCKS, 256, 0, s1>>>(up_facts, ufT);
    cudaEventRecord(eC, s1);

    // A: up_decoder transpose + rowptr on s0.
    prep_ud_kernel<<<T1_BLOCKS + RP_BLOCKS, 256>>>(up_decoder, i_indices, udT);

    // B: values on s0, PDL-overlapped with A's tail.
    {
        int threads = 256;
        long long total_threads = (long long)FDIM * 2 * 32;
        int blocks = (int)((total_threads + threads - 1) / threads);

        cudaLaunchConfig_t cfg = {};
        cfg.gridDim  = dim3((unsigned)blocks);
        cfg.blockDim = dim3((unsigned)threads);
        cfg.dynamicSmemBytes = 0;
        cfg.stream = 0;
        cudaLaunchAttribute attr[1];
        attr[0].id = cudaLaunchAttributeProgrammaticStreamSerialization;
        attr[0].val.programmaticStreamSerializationAllowed = 1;
        cfg.attrs = attr;
        cfg.numAttrs = 1;
        cudaLaunchKernelEx(&cfg, values_kernel, down_encoder, j_indices);
    }

    // Join: spmm needs ufT from s1.
    cudaStreamWaitEvent(0, eC, 0);

    // D: fused SpMM + output transpose, PDL-overlapped with values' tail.
    {
        cudaLaunchConfig_t cfg = {};
        cfg.gridDim  = dim3(FDIM / TI, BS / TT);
        cfg.blockDim = dim3(256);
        cfg.dynamicSmemBytes = 0;
        cfg.stream = 0;
        cudaLaunchAttribute attr[1];
        attr[0].id = cudaLaunchAttributeProgrammaticStreamSerialization;
        attr[0].val.programmaticStreamSerializationAllowed = 1;
        cfg.attrs = attr;
        cfg.numAttrs = 1;
        cudaLaunchKernelEx(&cfg, spmm_fused_kernel, j_indices, out);
    }
}

// round 13
// speedup vs baseline: 1.0937x; 1.0029x over previous
#include <cuda_runtime.h>
#include <cuda_fp16.h>
#include <cstdint>

// Problem constants (fixed by the dataset)
#define BATCH 2
#define SEQ   512
#define BS    (BATCH * SEQ)      // 1024 tokens
#define FDIM  16384              // n_features
#define DDIM  768                // d_model
#define MCON  262144             // n_connections

// SpMM tile
#define TI 16    // i rows per block
#define TT 256   // tokens per block (lane owns 8 via one uint4 of halves)

// Prep grids (transpose tiles are 64 src rows x 32 src cols)
#define T1_BLOCKS ((FDIM / 32) * (DDIM / 64))   // 6144 up_decoder tiles
#define T2_BLOCKS ((FDIM / 32) * (BS / 64))     // 8192 up_facts tiles
#define RP_BLOCKS (((FDIM + 1) + 255) / 256)    // 65 rowptr blocks

// Static device scratch (no allocations allowed in kernel_launch)
__device__ __half g_udT[(size_t)FDIM * DDIM];    // up_decoder transposed: [F, D], fp16
__device__ __half g_ufT[(size_t)FDIM * BS];      // up_facts transposed:   [F, BS], fp16
__device__ float  g_values[MCON];                // per-connection value (fp32)
__device__ int    g_rowptr[FDIM + 1];            // CSR row pointers over sorted i

// ---------------------------------------------------------------------------
// Transpose tile helper (R7-tuned): 64 src rows x 32 src cols, fp32 -> fp16,
// half2-vectorized gmem stores (full 128B transactions).
// ---------------------------------------------------------------------------
__device__ __forceinline__ void transpose_tile_f2h(const float* __restrict__ src,
                                                   __half* __restrict__ dst,
                                                   int R, int C, int bx, int by,
                                                   int x, int y) {
    __shared__ float tile[64][33];
    const int c0 = bx * 32;
    const int r0 = by * 64;

#pragma unroll
    for (int k = 0; k < 64; k += 8) {
        tile[y + k][x] = src[(size_t)(r0 + y + k) * C + c0 + x];
    }
    __syncthreads();

    __half2* dst2 = reinterpret_cast<__half2*>(dst);
    const int rhalf = R >> 1;
#pragma unroll
    for (int dr = 0; dr < 32; dr += 8) {
        int row = dr + y;             // src col / dst row within tile
        __half2 v = __floats2half2_rn(tile[2 * x][row], tile[2 * x + 1][row]);
        dst2[(size_t)(c0 + row) * rhalf + (r0 >> 1) + x] = v;
    }
}

// ---------------------------------------------------------------------------
// Kernel A: up_decoder transpose + rowptr (everything values_kernel needs).
// ---------------------------------------------------------------------------
__global__ void prep_ud_kernel(const float* __restrict__ up_decoder,
                               const int* __restrict__ i_indices,
                               __half* __restrict__ udT) {
    cudaTriggerProgrammaticLaunchCompletion();
    const int b = blockIdx.x;
    const int x = threadIdx.x & 31;
    const int y = threadIdx.x >> 5;

    if (b < T1_BLOCKS) {
        int bx = b % (FDIM / 32);
        int by = b / (FDIM / 32);
        transpose_tile_f2h(up_decoder, udT, DDIM, FDIM, bx, by, x, y);
    } else {
        // rowptr: g_rowptr[f] = lower_bound(i_indices, f)
        int f = (b - T1_BLOCKS) * 256 + threadIdx.x;
        if (f > FDIM) return;
        int lo = 0, hi = MCON;
        while (lo < hi) {
            int mid = (lo + hi) >> 1;
            if (i_indices[mid] < f) lo = mid + 1;
            else hi = mid;
        }
        g_rowptr[f] = lo;
    }
}

// ---------------------------------------------------------------------------
// Kernel C (side stream): up_facts transpose — DRAM-bound, overlaps the
// L2-bound values_kernel.
// ---------------------------------------------------------------------------
__global__ void prep_uf_kernel(const float* __restrict__ up_facts,
                               __half* __restrict__ ufT) {
    const int b = blockIdx.x;
    const int x = threadIdx.x & 31;
    const int y = threadIdx.x >> 5;
    int bx = b % (FDIM / 32);
    int by = b / (FDIM / 32);
    transpose_tile_f2h(up_facts, ufT, BS, FDIM, bx, by, x, y);
}

// ---------------------------------------------------------------------------
// Kernel B: SDDMM values. TWO warps per i-row (even/odd m split).
// E[i] held fp32 in registers, layout-matched to the fp16 U row loads.
// 32-bit index math (j*DDIM <= 12.6M fits int).
// PDL: E loads (independent of prep) run before the grid sync.
// ---------------------------------------------------------------------------
__global__ void values_kernel(const float* __restrict__ down_encoder,
                              const int* __restrict__ j_indices) {
    cudaTriggerProgrammaticLaunchCompletion();
    int gwarp = (blockIdx.x * blockDim.x + threadIdx.x) >> 5;
    int lane = threadIdx.x & 31;
    if (gwarp >= FDIM * 2) {
        cudaGridDependencySynchronize();
        return;
    }
    const int i      = gwarp >> 1;
    const int parity = gwarp & 1;

    // Prologue independent of prep: load E[i].
    const float4* E4 = reinterpret_cast<const float4*>(down_encoder) + i * (DDIM / 4);
    float4 ea[3], eb[3];
#pragma unroll
    for (int k = 0; k < 3; k++) {
        int base = 2 * (k * 32 + lane);
        ea[k] = E4[base];
        eb[k] = E4[base + 1];
    }

    // Wait for prep_ud (udT + rowptr) to be complete and visible.
    cudaGridDependencySynchronize();

    const uint4* ud = reinterpret_cast<const uint4*>(g_udT);
    int m1 = g_rowptr[i + 1];
    for (int m = g_rowptr[i] + parity; m < m1; m += 2) {
        int j = __ldg(&j_indices[m]);
        const uint4* U = ud + j * (DDIM / 8);   // 32-bit mul
        float s = 0.0f;
#pragma unroll
        for (int k = 0; k < 3; k++) {
            uint4 u = U[k * 32 + lane];
            float2 f0 = __half22float2(*reinterpret_cast<__half2*>(&u.x));
            float2 f1 = __half22float2(*reinterpret_cast<__half2*>(&u.y));
            float2 f2 = __half22float2(*reinterpret_cast<__half2*>(&u.z));
            float2 f3 = __half22float2(*reinterpret_cast<__half2*>(&u.w));
            s += ea[k].x * f0.x + ea[k].y * f0.y + ea[k].z * f1.x + ea[k].w * f1.y;
            s += eb[k].x * f2.x + eb[k].y * f2.y + eb[k].z * f3.x + eb[k].w * f3.y;
        }
#pragma unroll
        for (int off = 16; off; off >>= 1)
            s += __shfl_xor_sync(0xffffffffu, s, off);
        if (lane == 0) g_values[m] = s;
    }
}

// ---------------------------------------------------------------------------
// FMA helper: acc[0..7] += v * (8 halves in u)
// ---------------------------------------------------------------------------
__device__ __forceinline__ void fma8(float* acc, float v, const uint4& u) {
    float2 f0 = __half22float2(*reinterpret_cast<const __half2*>(&u.x));
    float2 f1 = __half22float2(*reinterpret_cast<const __half2*>(&u.y));
    float2 f2 = __half22float2(*reinterpret_cast<const __half2*>(&u.z));
    float2 f3 = __half22float2(*reinterpret_cast<const __half2*>(&u.w));
    acc[0] += v * f0.x; acc[1] += v * f0.y;
    acc[2] += v * f1.x; acc[3] += v * f1.y;
    acc[4] += v * f2.x; acc[5] += v * f2.y;
    acc[6] += v * f3.x; acc[7] += v * f3.y;
}

// ---------------------------------------------------------------------------
// Kernel D: fused SpMM + output transpose, fp16 activations, fp32 accumulate.
// Block computes [TI=16 i-rows] x [TT=256 tokens]. Warp handles 2 i-rows;
// lane owns 8 consecutive tokens. 4-way m-unroll for 4 independent
// j->u gather chains per warp. 32-bit index math throughout; regs capped
// for 6 blocks/SM (75% occ).
// ---------------------------------------------------------------------------
__global__ void __launch_bounds__(256, 6)
spmm_fused_kernel(const int* __restrict__ j_indices,
                  float* __restrict__ out) {
    cudaGridDependencySynchronize();

    __shared__ float tile[TI][TT + 1];   // pad 1: conflict-free column reads

    const int i_base = blockIdx.x * TI;
    const int tok0   = blockIdx.y * TT;
    const int warp   = threadIdx.x >> 5;
    const int lane   = threadIdx.x & 31;

    const uint4* uf = reinterpret_cast<const uint4*>(g_ufT);
    const int tcol = (tok0 >> 3) + lane;   // uint4 index into a ufT row (BS/8 per row)

    for (int ii = warp; ii < TI; ii += 8) {
        const int i = i_base + ii;
        int m0 = g_rowptr[i];
        int m1 = g_rowptr[i + 1];

        float acc[8];
#pragma unroll
        for (int t = 0; t < 8; t++) acc[t] = 0.0f;

        int m = m0;
        // 4-way unroll: 4 independent j->u chains in flight. 32-bit offsets.
        for (; m + 3 < m1; m += 4) {
            int o0 = __ldg(&j_indices[m])     * (BS / 8) + tcol;
            int o1 = __ldg(&j_indices[m + 1]) * (BS / 8) + tcol;
            int o2 = __ldg(&j_indices[m + 2]) * (BS / 8) + tcol;
            int o3 = __ldg(&j_indices[m + 3]) * (BS / 8) + tcol;
            float v0 = g_values[m];
            float v1 = g_values[m + 1];
            float v2 = g_values[m + 2];
            float v3 = g_values[m + 3];
            uint4 u0 = uf[o0];
            uint4 u1 = uf[o1];
            uint4 u2 = uf[o2];
            uint4 u3 = uf[o3];
            fma8(acc, v0, u0);
            fma8(acc, v1, u1);
            fma8(acc, v2, u2);
            fma8(acc, v3, u3);
        }
        for (; m < m1; m++) {
            int o = __ldg(&j_indices[m]) * (BS / 8) + tcol;
            float v = g_values[m];
            uint4 u = uf[o];
            fma8(acc, v, u);
        }

#pragma unroll
        for (int t = 0; t < 8; t++)
            tile[ii][lane * 8 + t] = acc[t];
    }
    __syncthreads();

    // Write out: each half-warp writes one token row of 16 consecutive i's
    // (64B), two rows per warp per iteration. 32-bit out indexing.
    {
        const int il = lane & 15;
        const int obase = tok0 * FDIM + i_base + il;
        for (int t = warp * 2 + (lane >> 4); t < TT; t += 16) {
            out[obase + t * FDIM] = tile[il][t];
        }
    }
}

// ---------------------------------------------------------------------------
// Launch DAG:
//   s0: A(ud transpose + rowptr) -> B(values, PDL) -> [wait C] -> D(spmm)
//   s1: C(uf transpose)   (forked from s0, joined before D)
// ---------------------------------------------------------------------------
extern "C" void kernel_launch(void* const* d_in, const int* in_sizes, int n_in,
                              void* d_out, int out_size) {
    const float* up_facts     = (const float*)d_in[0];   // [B, S, F]
    const float* down_encoder = (const float*)d_in[1];   // [F, D]
    const float* up_decoder   = (const float*)d_in[2];   // [D, F]
    const int*   i_indices    = (const int*)d_in[3];     // [M], sorted, int32
    const int*   j_indices    = (const int*)d_in[4];     // [M], int32
    float*       out          = (float*)d_out;           // [B, S, F]

    __half* udT; cudaGetSymbolAddress((void**)&udT, g_udT);
    __half* ufT; cudaGetSymbolAddress((void**)&ufT, g_ufT);

    // Host-side handles: created per call, intentionally NOT destroyed.
    // kernel_launch only executes for correctness + graph capture (replays
    // use the captured graph), so this leaks a handful of host objects, and
    // avoids destroying a stream/event that the active capture references.
    cudaStream_t s1;
    cudaStreamCreateWithFlags(&s1, cudaStreamNonBlocking);
    cudaEvent_t eFork, eC;
    cudaEventCreateWithFlags(&eFork, cudaEventDisableTiming);
    cudaEventCreateWithFlags(&eC, cudaEventDisableTiming);

    // Fork side stream from the (captured) default stream.
    cudaEventRecord(eFork, 0);
    cudaStreamWaitEvent(s1, eFork, 0);

    // C: up_facts transpose on s1 (independent; joined before spmm).
    prep_uf_kernel<<<T2_BLOCKS, 256, 0, s1>>>(up_facts, ufT);
    cudaEventRecord(eC, s1);

    // A: up_decoder transpose + rowptr on s0.
    prep_ud_kernel<<<T1_BLOCKS + RP_BLOCKS, 256>>>(up_decoder, i_indices, udT);

    // B: values on s0, PDL-overlapped with A's tail.
    {
        int threads = 256;
        long long total_threads = (long long)FDIM * 2 * 32;
        int blocks = (int)((total_threads + threads - 1) / threads);

        cudaLaunchConfig_t cfg = {};
        cfg.gridDim  = dim3((unsigned)blocks);
        cfg.blockDim = dim3((unsigned)threads);
        cfg.dynamicSmemBytes = 0;
        cfg.stream = 0;
        cudaLaunchAttribute attr[1];
        attr[0].id = cudaLaunchAttributeProgrammaticStreamSerialization;
        attr[0].val.programmaticStreamSerializationAllowed = 1;
        cfg.attrs = attr;
        cfg.numAttrs = 1;
        cudaLaunchKernelEx(&cfg, values_kernel, down_encoder, j_indices);
    }

    // Join: spmm needs ufT from s1.
    cudaStreamWaitEvent(0, eC, 0);

    // D: fused SpMM + output transpose, PDL-overlapped with values' tail.
    {
        cudaLaunchConfig_t cfg = {};
        cfg.gridDim  = dim3(FDIM / TI, BS / TT);
        cfg.blockDim = dim3(256);
        cfg.dynamicSmemBytes = 0;
        cfg.stream = 0;
        cudaLaunchAttribute attr[1];
        attr[0].id = cudaLaunchAttributeProgrammaticStreamSerialization;
        attr[0].val.programmaticStreamSerializationAllowed = 1;
        cfg.attrs = attr;
        cfg.numAttrs = 1;
        cudaLaunchKernelEx(&cfg, spmm_fused_kernel, j_indices, out);
    }
}

// round 14
// speedup vs baseline: 1.0971x; 1.0031x over previous
#include <cuda_runtime.h>
#include <cuda_fp16.h>
#include <cstdint>

// Problem constants (fixed by the dataset)
#define BATCH 2
#define SEQ   512
#define BS    (BATCH * SEQ)      // 1024 tokens
#define FDIM  16384              // n_features
#define DDIM  768                // d_model
#define MCON  262144             // n_connections

// SpMM tile
#define TI 16    // i rows per block
#define TT 256   // tokens per block (lane owns 8 via one uint4 of halves)

// Prep grids (transpose tiles are 64 src rows x 32 src cols)
#define T1_BLOCKS ((FDIM / 32) * (DDIM / 64))   // 6144 up_decoder tiles
#define T2_BLOCKS ((FDIM / 32) * (BS / 64))     // 8192 up_facts tiles
#define RP_BLOCKS (((FDIM + 1) + 255) / 256)    // 65 rowptr blocks

// Static device scratch (no allocations allowed in kernel_launch)
__device__ __half g_udT[(size_t)FDIM * DDIM];    // up_decoder transposed: [F, D], fp16
__device__ __half g_ufT[(size_t)FDIM * BS];      // up_facts transposed:   [F, BS], fp16
__device__ float  g_values[MCON];                // per-connection value (fp32)
__device__ int    g_rowptr[FDIM + 1];            // CSR row pointers over sorted i

// ---------------------------------------------------------------------------
// Transpose tile helper (R7-tuned): 64 src rows x 32 src cols, fp32 -> fp16,
// half2-vectorized gmem stores (full 128B transactions).
// ---------------------------------------------------------------------------
__device__ __forceinline__ void transpose_tile_f2h(const float* __restrict__ src,
                                                   __half* __restrict__ dst,
                                                   int R, int C, int bx, int by,
                                                   int x, int y) {
    __shared__ float tile[64][33];
    const int c0 = bx * 32;
    const int r0 = by * 64;

#pragma unroll
    for (int k = 0; k < 64; k += 8) {
        tile[y + k][x] = src[(size_t)(r0 + y + k) * C + c0 + x];
    }
    __syncthreads();

    __half2* dst2 = reinterpret_cast<__half2*>(dst);
    const int rhalf = R >> 1;
#pragma unroll
    for (int dr = 0; dr < 32; dr += 8) {
        int row = dr + y;             // src col / dst row within tile
        __half2 v = __floats2half2_rn(tile[2 * x][row], tile[2 * x + 1][row]);
        dst2[(size_t)(c0 + row) * rhalf + (r0 >> 1) + x] = v;
    }
}

// ---------------------------------------------------------------------------
// Kernel A: up_decoder transpose + rowptr (everything values_kernel needs).
// ---------------------------------------------------------------------------
__global__ void prep_ud_kernel(const float* __restrict__ up_decoder,
                               const int* __restrict__ i_indices,
                               __half* __restrict__ udT) {
    cudaTriggerProgrammaticLaunchCompletion();
    const int b = blockIdx.x;
    const int x = threadIdx.x & 31;
    const int y = threadIdx.x >> 5;

    if (b < T1_BLOCKS) {
        int bx = b % (FDIM / 32);
        int by = b / (FDIM / 32);
        transpose_tile_f2h(up_decoder, udT, DDIM, FDIM, bx, by, x, y);
    } else {
        // rowptr: g_rowptr[f] = lower_bound(i_indices, f)
        int f = (b - T1_BLOCKS) * 256 + threadIdx.x;
        if (f > FDIM) return;
        int lo = 0, hi = MCON;
        while (lo < hi) {
            int mid = (lo + hi) >> 1;
            if (i_indices[mid] < f) lo = mid + 1;
            else hi = mid;
        }
        g_rowptr[f] = lo;
    }
}

// ---------------------------------------------------------------------------
// Kernel C (side stream): up_facts transpose — DRAM-bound, overlaps the
// L2-bound values_kernel.
// ---------------------------------------------------------------------------
__global__ void prep_uf_kernel(const float* __restrict__ up_facts,
                               __half* __restrict__ ufT) {
    const int b = blockIdx.x;
    const int x = threadIdx.x & 31;
    const int y = threadIdx.x >> 5;
    int bx = b % (FDIM / 32);
    int by = b / (FDIM / 32);
    transpose_tile_f2h(up_facts, ufT, BS, FDIM, bx, by, x, y);
}

// ---------------------------------------------------------------------------
// Kernel B: SDDMM values. TWO warps per i-row (even/odd m split).
// E[i] held fp32 in registers, layout-matched to the fp16 U row loads.
// 32-bit index math. PDL: E loads run before the grid sync.
// ---------------------------------------------------------------------------
__global__ void values_kernel(const float* __restrict__ down_encoder,
                              const int* __restrict__ j_indices) {
    cudaTriggerProgrammaticLaunchCompletion();
    int gwarp = (blockIdx.x * blockDim.x + threadIdx.x) >> 5;
    int lane = threadIdx.x & 31;
    if (gwarp >= FDIM * 2) {
        cudaGridDependencySynchronize();
        return;
    }
    const int i      = gwarp >> 1;
    const int parity = gwarp & 1;

    // Prologue independent of prep: load E[i].
    const float4* E4 = reinterpret_cast<const float4*>(down_encoder) + i * (DDIM / 4);
    float4 ea[3], eb[3];
#pragma unroll
    for (int k = 0; k < 3; k++) {
        int base = 2 * (k * 32 + lane);
        ea[k] = E4[base];
        eb[k] = E4[base + 1];
    }

    // Wait for prep_ud (udT + rowptr) to be complete and visible.
    cudaGridDependencySynchronize();

    const uint4* ud = reinterpret_cast<const uint4*>(g_udT);
    int m1 = g_rowptr[i + 1];
    for (int m = g_rowptr[i] + parity; m < m1; m += 2) {
        int j = __ldg(&j_indices[m]);
        const uint4* U = ud + j * (DDIM / 8);   // 32-bit mul
        float s = 0.0f;
#pragma unroll
        for (int k = 0; k < 3; k++) {
            uint4 u = U[k * 32 + lane];
            float2 f0 = __half22float2(*reinterpret_cast<__half2*>(&u.x));
            float2 f1 = __half22float2(*reinterpret_cast<__half2*>(&u.y));
            float2 f2 = __half22float2(*reinterpret_cast<__half2*>(&u.z));
            float2 f3 = __half22float2(*reinterpret_cast<__half2*>(&u.w));
            s += ea[k].x * f0.x + ea[k].y * f0.y + ea[k].z * f1.x + ea[k].w * f1.y;
            s += eb[k].x * f2.x + eb[k].y * f2.y + eb[k].z * f3.x + eb[k].w * f3.y;
        }
#pragma unroll
        for (int off = 16; off; off >>= 1)
            s += __shfl_xor_sync(0xffffffffu, s, off);
        if (lane == 0) g_values[m] = s;
    }
}

// ---------------------------------------------------------------------------
// FMA helper: acc[0..7] += v * (8 halves in u)
// ---------------------------------------------------------------------------
__device__ __forceinline__ void fma8(float* acc, float v, const uint4& u) {
    float2 f0 = __half22float2(*reinterpret_cast<const __half2*>(&u.x));
    float2 f1 = __half22float2(*reinterpret_cast<const __half2*>(&u.y));
    float2 f2 = __half22float2(*reinterpret_cast<const __half2*>(&u.z));
    float2 f3 = __half22float2(*reinterpret_cast<const __half2*>(&u.w));
    acc[0] += v * f0.x; acc[1] += v * f0.y;
    acc[2] += v * f1.x; acc[3] += v * f1.y;
    acc[4] += v * f2.x; acc[5] += v * f2.y;
    acc[6] += v * f3.x; acc[7] += v * f3.y;
}

// ---------------------------------------------------------------------------
// Kernel D: fused SpMM + output transpose, fp16 activations, fp32 accumulate.
// Block computes [TI=16 i-rows] x [TT=256 tokens]. Warp handles 2 i-rows;
// lane owns 8 consecutive tokens. 4-way m-unroll with VECTORIZED metadata:
// one int4 (j's) + one float4 (values) per 4 m's instead of 8 scalar loads
// -> 18 L1tex wavefronts per 4 m's instead of 24 (the kernel is L1tex-bound).
// m aligned to 4 via scalar prologue so the 16B loads are aligned.
// ---------------------------------------------------------------------------
__global__ void __launch_bounds__(256, 6)
spmm_fused_kernel(const int* __restrict__ j_indices,
                  float* __restrict__ out) {
    cudaGridDependencySynchronize();

    __shared__ float tile[TI][TT + 1];   // pad 1: conflict-free column reads

    const int i_base = blockIdx.x * TI;
    const int tok0   = blockIdx.y * TT;
    const int warp   = threadIdx.x >> 5;
    const int lane   = threadIdx.x & 31;

    const uint4* uf = reinterpret_cast<const uint4*>(g_ufT);
    const int tcol = (tok0 >> 3) + lane;   // uint4 index into a ufT row (BS/8 per row)

    for (int ii = warp; ii < TI; ii += 8) {
        const int i = i_base + ii;
        int m0 = g_rowptr[i];
        int m1 = g_rowptr[i + 1];

        float acc[8];
#pragma unroll
        for (int t = 0; t < 8; t++) acc[t] = 0.0f;

        int m = m0;
        // Prologue: scalar until m is 16B-aligned (multiple of 4).
        for (; m < m1 && (m & 3); m++) {
            int o = __ldg(&j_indices[m]) * (BS / 8) + tcol;
            float v = g_values[m];
            uint4 u = uf[o];
            fma8(acc, v, u);
        }
        // Main: 4 m's per iter, vectorized j/value loads (1+1 wavefronts),
        // 4 independent gather chains.
        for (; m + 3 < m1; m += 4) {
            int4   j4 = *reinterpret_cast<const int4*>(j_indices + m);
            float4 v4 = *reinterpret_cast<const float4*>(g_values + m);
            int o0 = j4.x * (BS / 8) + tcol;
            int o1 = j4.y * (BS / 8) + tcol;
            int o2 = j4.z * (BS / 8) + tcol;
            int o3 = j4.w * (BS / 8) + tcol;
            uint4 u0 = uf[o0];
            uint4 u1 = uf[o1];
            uint4 u2 = uf[o2];
            uint4 u3 = uf[o3];
            fma8(acc, v4.x, u0);
            fma8(acc, v4.y, u1);
            fma8(acc, v4.z, u2);
            fma8(acc, v4.w, u3);
        }
        // Tail.
        for (; m < m1; m++) {
            int o = __ldg(&j_indices[m]) * (BS / 8) + tcol;
            float v = g_values[m];
            uint4 u = uf[o];
            fma8(acc, v, u);
        }

#pragma unroll
        for (int t = 0; t < 8; t++)
            tile[ii][lane * 8 + t] = acc[t];
    }
    __syncthreads();

    // Write out: each half-warp writes one token row of 16 consecutive i's
    // (64B), two rows per warp per iteration. 32-bit out indexing.
    {
        const int il = lane & 15;
        const int obase = tok0 * FDIM + i_base + il;
        for (int t = warp * 2 + (lane >> 4); t < TT; t += 16) {
            out[obase + t * FDIM] = tile[il][t];
        }
    }
}

// ---------------------------------------------------------------------------
// Launch DAG:
//   s0: A(ud transpose + rowptr) -> B(values, PDL) -> [wait C] -> D(spmm)
//   s1: C(uf transpose)   (forked from s0, joined before D)
// ---------------------------------------------------------------------------
extern "C" void kernel_launch(void* const* d_in, const int* in_sizes, int n_in,
                              void* d_out, int out_size) {
    const float* up_facts     = (const float*)d_in[0];   // [B, S, F]
    const float* down_encoder = (const float*)d_in[1];   // [F, D]
    const float* up_decoder   = (const float*)d_in[2];   // [D, F]
    const int*   i_indices    = (const int*)d_in[3];     // [M], sorted, int32
    const int*   j_indices    = (const int*)d_in[4];     // [M], int32
    float*       out          = (float*)d_out;           // [B, S, F]

    __half* udT; cudaGetSymbolAddress((void**)&udT, g_udT);
    __half* ufT; cudaGetSymbolAddress((void**)&ufT, g_ufT);

    // Host-side handles: created per call, intentionally NOT destroyed.
    // kernel_launch only executes for correctness + graph capture (replays
    // use the captured graph), so this leaks a handful of host objects, and
    // avoids destroying a stream/event that the active capture references.
    cudaStream_t s1;
    cudaStreamCreateWithFlags(&s1, cudaStreamNonBlocking);
    cudaEvent_t eFork, eC;
    cudaEventCreateWithFlags(&eFork, cudaEventDisableTiming);
    cudaEventCreateWithFlags(&eC, cudaEventDisableTiming);

    // Fork side stream from the (captured) default stream.
    cudaEventRecord(eFork, 0);
    cudaStreamWaitEvent(s1, eFork, 0);

    // C: up_facts transpose on s1 (independent; joined before spmm).
    prep_uf_kernel<<<T2_BLOCKS, 256, 0, s1>>>(up_facts, ufT);
    cudaEventRecord(eC, s1);

    // A: up_decoder transpose + rowptr on s0.
    prep_ud_kernel<<<T1_BLOCKS + RP_BLOCKS, 256>>>(up_decoder, i_indices, udT);

    // B: values on s0, PDL-overlapped with A's tail.
    {
        int threads = 256;
        long long total_threads = (long long)FDIM * 2 * 32;
        int blocks = (int)((total_threads + threads - 1) / threads);

        cudaLaunchConfig_t cfg = {};
        cfg.gridDim  = dim3((unsigned)blocks);
        cfg.blockDim = dim3((unsigned)threads);
        cfg.dynamicSmemBytes = 0;
        cfg.stream = 0;
        cudaLaunchAttribute attr[1];
        attr[0].id = cudaLaunchAttributeProgrammaticStreamSerialization;
        attr[0].val.programmaticStreamSerializationAllowed = 1;
        cfg.attrs = attr;
        cfg.numAttrs = 1;
        cudaLaunchKernelEx(&cfg, values_kernel, down_encoder, j_indices);
    }

    // Join: spmm needs ufT from s1.
    cudaStreamWaitEvent(0, eC, 0);

    // D: fused SpMM + output transpose, PDL-overlapped with values' tail.
    {
        cudaLaunchConfig_t cfg = {};
        cfg.gridDim  = dim3(FDIM / TI, BS / TT);
        cfg.blockDim = dim3(256);
        cfg.dynamicSmemBytes = 0;
        cfg.stream = 0;
        cudaLaunchAttribute attr[1];
        attr[0].id = cudaLaunchAttributeProgrammaticStreamSerialization;
        attr[0].val.programmaticStreamSerializationAllowed = 1;
        cfg.attrs = attr;
        cfg.numAttrs = 1;
        cudaLaunchKernelEx(&cfg, spmm_fused_kernel, j_indices, out);
    }
}